// round 5
// baseline (speedup 1.0000x reference)
#include <cuda_runtime.h>
#include <math.h>
#include <stdint.h>

#define Bsz   32
#define Nn    4096
#define DIN   768
#define DS    256
#define KSL   8
#define DH    128
#define NITER 3
#define MROWS (Bsz*Nn)   // 131072

// ------------------------- scratch (device globals, no allocs) -------------
__device__ float g_pool_part[Bsz*8*DIN];
__device__ float g_pool[Bsz*DIN];
__device__ float g_t1[Bsz*512];
__device__ float g_slots[Bsz*KSL*DS];
__device__ float g_inputs[MROWS*DS];      // 134 MB
__device__ float g_kcat[MROWS*DS];        // 134 MB
__device__ float g_qcat[Bsz*KSL*DS];
__device__ float g_attn[Bsz*KSL*Nn];
__device__ float g_rowsum_part[Bsz*KSL*128];
__device__ float g_upd_part[Bsz*16*KSL*DS];

__device__ __forceinline__ float gelu_exact(float x) {
    return 0.5f * x * (1.0f + erff(x * 0.70710678118654752f));
}
__device__ __forceinline__ float sigmoidf_(float x) {
    return 1.0f / (1.0f + expf(-x));
}
__device__ __forceinline__ void mma_tf32(float* c, const uint32_t* a,
                                         uint32_t b0, uint32_t b1) {
    asm volatile(
        "mma.sync.aligned.m16n8k8.row.col.f32.tf32.tf32.f32 "
        "{%0,%1,%2,%3}, {%4,%5,%6,%7}, {%8,%9}, {%0,%1,%2,%3};\n"
        : "+f"(c[0]), "+f"(c[1]), "+f"(c[2]), "+f"(c[3])
        : "r"(a[0]), "r"(a[1]), "r"(a[2]), "r"(a[3]), "r"(b0), "r"(b1));
}
__device__ __forceinline__ void cp16(uint32_t* smem_dst, const float* gsrc) {
    unsigned sa = (unsigned)__cvta_generic_to_shared(smem_dst);
    asm volatile("cp.async.cg.shared.global [%0], [%1], 16;\n"
                 :: "r"(sa), "l"(gsrc));
}
__device__ __forceinline__ void cp_commit() {
    asm volatile("cp.async.commit_group;\n");
}
template <int N>
__device__ __forceinline__ void cp_wait() {
    asm volatile("cp.async.wait_group %0;\n" :: "n"(N));
}

extern __shared__ uint32_t g_dyn[];

// ------------------------- 1) feature pooling ------------------------------
__global__ void pool_part_kernel(const float* __restrict__ feat) {
    int d  = blockIdx.x * 256 + threadIdx.x;   // < 768
    int nc = blockIdx.y;
    int b  = blockIdx.z;
    float s = 0.f;
    const float* p = feat + (size_t)(b * Nn + nc * 512) * DIN + d;
    for (int n = 0; n < 512; ++n) s += p[(size_t)n * DIN];
    g_pool_part[(b * 8 + nc) * DIN + d] = s;
}
__global__ void pool_reduce_kernel() {
    int d = blockIdx.x * 256 + threadIdx.x;
    int b = blockIdx.y;
    float s = 0.f;
    for (int i = 0; i < 8; ++i) s += g_pool_part[(b * 8 + i) * DIN + d];
    g_pool[b * DIN + d] = s * (1.0f / (float)Nn);
}

// ------------------------- 2) slot init MLP --------------------------------
__global__ void slots_init1_kernel(const float* __restrict__ Wi1,
                                   const float* __restrict__ bi1) {
    __shared__ float s_pool[DIN];
    int t = threadIdx.x;
    int b = blockIdx.y;
    int j = blockIdx.x * 256 + t;              // < 512
    for (int i = t; i < DIN; i += 256) s_pool[i] = g_pool[b * DIN + i];
    __syncthreads();
    float acc = bi1[j];
    for (int k = 0; k < DIN; ++k) acc += s_pool[k] * Wi1[k * 512 + j];
    g_t1[b * 512 + j] = gelu_exact(acc);
}
__global__ void slots_init2_kernel(const float* __restrict__ Wi2,
                                   const float* __restrict__ bi2) {
    __shared__ float s_t[512];
    int t = threadIdx.x;
    int b = blockIdx.y;
    int j = blockIdx.x * 256 + t;              // < 2048
    s_t[t] = g_t1[b * 512 + t];
    s_t[t + 256] = g_t1[b * 512 + t + 256];
    __syncthreads();
    float acc = bi2[j];
    for (int k = 0; k < 512; ++k) acc += s_t[k] * Wi2[k * 2048 + j];
    g_slots[b * 2048 + j] = acc;
}

// ------------------------- 3) tf32 TC GEMM + fused LN (pipelined) ----------
// inputs = LN(feat @ Wp + bp). BM=128, BN=256, BK=32, 256 threads (8 warps,
// 2x4), warp tile 64x64 (4 mt x 8 nt), 2-stage cp.async.
#define GL_AS_STRIDE 36
#define GL_BS_STRIDE 264
#define GL_AS_SZ (128*GL_AS_STRIDE)     // 4608
#define GL_BS_SZ (32*GL_BS_STRIDE)      // 8448
#define GL_SMEM_BYTES ((2*GL_AS_SZ + 2*GL_BS_SZ)*4)   // 104448

__device__ __forceinline__ void gl_load_stage(
    uint32_t* As, uint32_t* Bs, const float* __restrict__ feat,
    const float* __restrict__ Wp, int bRow, int k0, int t) {
#pragma unroll
    for (int i = 0; i < 4; ++i) {
        int idx = t + 256 * i;                 // 0..1023
        int row = idx >> 3, q = idx & 7;
        cp16(&As[row * GL_AS_STRIDE + q * 4],
             &feat[(size_t)(bRow + row) * DIN + k0 + q * 4]);
    }
#pragma unroll
    for (int i = 0; i < 8; ++i) {
        int idx = t + 256 * i;                 // 0..2047
        int kk = idx >> 6, cq = idx & 63;
        cp16(&Bs[kk * GL_BS_STRIDE + cq * 4],
             &Wp[(size_t)(k0 + kk) * 256 + cq * 4]);
    }
}

__global__ void __launch_bounds__(256)
gemm_ln_tc(const float* __restrict__ feat, const float* __restrict__ Wp,
           const float* __restrict__ bp, const float* __restrict__ lng,
           const float* __restrict__ lnb) {
    uint32_t* AsBuf = g_dyn;
    uint32_t* BsBuf = g_dyn + 2 * GL_AS_SZ;
    __shared__ float s_sum[128][4];
    __shared__ float s_sq[128][4];

    int t = threadIdx.x;
    int lane = t & 31, wid = t >> 5;
    int wr = wid >> 2, wc = wid & 3;    // 2x4 warps: 64 rows x 64 cols each
    int g = lane >> 2, tg = lane & 3;
    int bRow = blockIdx.x * 128;

    float c[4][8][4];
#pragma unroll
    for (int mt = 0; mt < 4; ++mt)
#pragma unroll
        for (int nt = 0; nt < 8; ++nt)
#pragma unroll
            for (int j = 0; j < 4; ++j) c[mt][nt][j] = 0.f;

    gl_load_stage(AsBuf, BsBuf, feat, Wp, bRow, 0, t);
    cp_commit();

    const int NK = DIN / 32;    // 24
    for (int kt = 0; kt < NK; ++kt) {
        int s = kt & 1;
        if (kt + 1 < NK) {
            gl_load_stage(AsBuf + ((kt + 1) & 1) * GL_AS_SZ,
                          BsBuf + ((kt + 1) & 1) * GL_BS_SZ,
                          feat, Wp, bRow, (kt + 1) * 32, t);
            cp_commit();
            cp_wait<1>();
        } else {
            cp_wait<0>();
        }
        __syncthreads();
        uint32_t* As = AsBuf + s * GL_AS_SZ;
        uint32_t* Bs = BsBuf + s * GL_BS_SZ;
#pragma unroll
        for (int ks = 0; ks < 4; ++ks) {
            uint32_t a[4][4];
#pragma unroll
            for (int mt = 0; mt < 4; ++mt) {
                int r = wr * 64 + mt * 16 + g;
                a[mt][0] = As[r * GL_AS_STRIDE + ks * 8 + tg];
                a[mt][1] = As[(r + 8) * GL_AS_STRIDE + ks * 8 + tg];
                a[mt][2] = As[r * GL_AS_STRIDE + ks * 8 + tg + 4];
                a[mt][3] = As[(r + 8) * GL_AS_STRIDE + ks * 8 + tg + 4];
            }
#pragma unroll
            for (int nt = 0; nt < 8; ++nt) {
                int cb = wc * 64 + nt * 8 + g;
                uint32_t b0 = Bs[(ks * 8 + tg) * GL_BS_STRIDE + cb];
                uint32_t b1 = Bs[(ks * 8 + tg + 4) * GL_BS_STRIDE + cb];
#pragma unroll
                for (int mt = 0; mt < 4; ++mt)
                    mma_tf32(c[mt][nt], a[mt], b0, b1);
            }
        }
        __syncthreads();
    }

    // --- epilogue: bias + LN over 256 cols, from register fragments ---
    float2 bpv[8], gv[8], bvv[8];
#pragma unroll
    for (int nt = 0; nt < 8; ++nt) {
        int cb = wc * 64 + nt * 8 + tg * 2;
        bpv[nt] = *reinterpret_cast<const float2*>(&bp[cb]);
        gv[nt]  = *reinterpret_cast<const float2*>(&lng[cb]);
        bvv[nt] = *reinterpret_cast<const float2*>(&lnb[cb]);
    }
    float ls[4][2], lq[4][2];
#pragma unroll
    for (int mt = 0; mt < 4; ++mt)
#pragma unroll
        for (int h = 0; h < 2; ++h) { ls[mt][h] = 0.f; lq[mt][h] = 0.f; }
#pragma unroll
    for (int mt = 0; mt < 4; ++mt)
#pragma unroll
        for (int nt = 0; nt < 8; ++nt) {
            c[mt][nt][0] += bpv[nt].x;
            c[mt][nt][1] += bpv[nt].y;
            c[mt][nt][2] += bpv[nt].x;
            c[mt][nt][3] += bpv[nt].y;
            ls[mt][0] += c[mt][nt][0] + c[mt][nt][1];
            lq[mt][0] += c[mt][nt][0] * c[mt][nt][0] + c[mt][nt][1] * c[mt][nt][1];
            ls[mt][1] += c[mt][nt][2] + c[mt][nt][3];
            lq[mt][1] += c[mt][nt][2] * c[mt][nt][2] + c[mt][nt][3] * c[mt][nt][3];
        }
#pragma unroll
    for (int mt = 0; mt < 4; ++mt)
#pragma unroll
        for (int h = 0; h < 2; ++h) {
            ls[mt][h] += __shfl_xor_sync(0xffffffffu, ls[mt][h], 1);
            ls[mt][h] += __shfl_xor_sync(0xffffffffu, ls[mt][h], 2);
            lq[mt][h] += __shfl_xor_sync(0xffffffffu, lq[mt][h], 1);
            lq[mt][h] += __shfl_xor_sync(0xffffffffu, lq[mt][h], 2);
        }
    if (tg == 0) {
#pragma unroll
        for (int mt = 0; mt < 4; ++mt)
#pragma unroll
            for (int h = 0; h < 2; ++h) {
                int rl = wr * 64 + mt * 16 + h * 8 + g;
                s_sum[rl][wc] = ls[mt][h];
                s_sq[rl][wc]  = lq[mt][h];
            }
    }
    __syncthreads();
    float mean[4][2], inv[4][2];
#pragma unroll
    for (int mt = 0; mt < 4; ++mt)
#pragma unroll
        for (int h = 0; h < 2; ++h) {
            int rl = wr * 64 + mt * 16 + h * 8 + g;
            float S = s_sum[rl][0] + s_sum[rl][1] + s_sum[rl][2] + s_sum[rl][3];
            float Q = s_sq[rl][0] + s_sq[rl][1] + s_sq[rl][2] + s_sq[rl][3];
            float m = S * (1.0f / 256.0f);
            float v = Q * (1.0f / 256.0f) - m * m;
            mean[mt][h] = m;
            inv[mt][h]  = rsqrtf(v + 1e-5f);
        }
#pragma unroll
    for (int mt = 0; mt < 4; ++mt)
#pragma unroll
        for (int nt = 0; nt < 8; ++nt)
#pragma unroll
            for (int h = 0; h < 2; ++h) {
                int rl = wr * 64 + mt * 16 + h * 8 + g;
                size_t row = (size_t)(bRow + rl);
                int cb = wc * 64 + nt * 8 + tg * 2;
                float2 o;
                o.x = (c[mt][nt][h * 2]     - mean[mt][h]) * inv[mt][h] * gv[nt].x + bvv[nt].x;
                o.y = (c[mt][nt][h * 2 + 1] - mean[mt][h]) * inv[mt][h] * gv[nt].y + bvv[nt].y;
                *reinterpret_cast<float2*>(&g_inputs[row * 256 + cb]) = o;
            }
}

// ------------------------- 4) tf32 TC k-projection (pipelined) -------------
// k_cat = [inp_s@Wks | inp_t@Wkt]. grid (1024, 2). BM=128, BN=128, BK=32,
// 256 threads (8 warps 2x4), warp tile 64x32 (4 mt x 4 nt).
#define KP_AS_STRIDE 36
#define KP_BS_STRIDE 136
#define KP_AS_SZ (128*KP_AS_STRIDE)     // 4608
#define KP_BS_SZ (32*KP_BS_STRIDE)      // 4352
#define KP_SMEM_BYTES ((2*KP_AS_SZ + 2*KP_BS_SZ)*4)   // 71680

__device__ __forceinline__ void kp_load_stage(
    uint32_t* As, uint32_t* Bs, const float* __restrict__ W,
    int bRow, int z, int k0, int t) {
#pragma unroll
    for (int i = 0; i < 4; ++i) {
        int idx = t + 256 * i;                 // 0..1023
        int row = idx >> 3, q = idx & 7;
        cp16(&As[row * KP_AS_STRIDE + q * 4],
             &g_inputs[(size_t)(bRow + row) * 256 + z * 128 + k0 + q * 4]);
    }
#pragma unroll
    for (int i = 0; i < 4; ++i) {
        int idx = t + 256 * i;                 // 0..1023
        int kk = idx >> 5, cq = idx & 31;
        cp16(&Bs[kk * KP_BS_STRIDE + cq * 4],
             &W[(size_t)(k0 + kk) * 128 + cq * 4]);
    }
}

__global__ void __launch_bounds__(256)
kproj_tc(const float* __restrict__ Wks, const float* __restrict__ Wkt) {
    uint32_t* AsBuf = g_dyn;
    uint32_t* BsBuf = g_dyn + 2 * KP_AS_SZ;

    int t = threadIdx.x;
    int lane = t & 31, wid = t >> 5;
    int wr = wid >> 2, wc = wid & 3;
    int g = lane >> 2, tg = lane & 3;
    int bRow = blockIdx.x * 128;
    int z = blockIdx.y;
    const float* W = z ? Wkt : Wks;

    float c[4][4][4];
#pragma unroll
    for (int mt = 0; mt < 4; ++mt)
#pragma unroll
        for (int nt = 0; nt < 4; ++nt)
#pragma unroll
            for (int j = 0; j < 4; ++j) c[mt][nt][j] = 0.f;

    kp_load_stage(AsBuf, BsBuf, W, bRow, z, 0, t);
    cp_commit();

    const int NK = 4;   // 128 / 32
    for (int kt = 0; kt < NK; ++kt) {
        int s = kt & 1;
        if (kt + 1 < NK) {
            kp_load_stage(AsBuf + ((kt + 1) & 1) * KP_AS_SZ,
                          BsBuf + ((kt + 1) & 1) * KP_BS_SZ,
                          W, bRow, z, (kt + 1) * 32, t);
            cp_commit();
            cp_wait<1>();
        } else {
            cp_wait<0>();
        }
        __syncthreads();
        uint32_t* As = AsBuf + s * KP_AS_SZ;
        uint32_t* Bs = BsBuf + s * KP_BS_SZ;
#pragma unroll
        for (int ks = 0; ks < 4; ++ks) {
            uint32_t a[4][4];
#pragma unroll
            for (int mt = 0; mt < 4; ++mt) {
                int r = wr * 64 + mt * 16 + g;
                a[mt][0] = As[r * KP_AS_STRIDE + ks * 8 + tg];
                a[mt][1] = As[(r + 8) * KP_AS_STRIDE + ks * 8 + tg];
                a[mt][2] = As[r * KP_AS_STRIDE + ks * 8 + tg + 4];
                a[mt][3] = As[(r + 8) * KP_AS_STRIDE + ks * 8 + tg + 4];
            }
#pragma unroll
            for (int nt = 0; nt < 4; ++nt) {
                int cb = wc * 32 + nt * 8 + g;
                uint32_t b0 = Bs[(ks * 8 + tg) * KP_BS_STRIDE + cb];
                uint32_t b1 = Bs[(ks * 8 + tg + 4) * KP_BS_STRIDE + cb];
#pragma unroll
                for (int mt = 0; mt < 4; ++mt)
                    mma_tf32(c[mt][nt], a[mt], b0, b1);
            }
        }
        __syncthreads();
    }
#pragma unroll
    for (int mt = 0; mt < 4; ++mt)
#pragma unroll
        for (int nt = 0; nt < 4; ++nt)
#pragma unroll
            for (int h = 0; h < 2; ++h) {
                int rl = wr * 64 + mt * 16 + h * 8 + g;
                size_t row = (size_t)(bRow + rl);
                int cb = wc * 32 + nt * 8 + tg * 2;
                float2 o;
                o.x = c[mt][nt][h * 2];
                o.y = c[mt][nt][h * 2 + 1];
                *reinterpret_cast<float2*>(&g_kcat[row * 256 + z * 128 + cb]) = o;
            }
}

// ------------------------- 5) q projection (scales prefolded) --------------
__global__ void qproj_kernel(const float* __restrict__ Wqs,
                             const float* __restrict__ Wqt) {
    __shared__ float s_slot[256];
    int t = threadIdx.x;
    int b = blockIdx.x, ks = blockIdx.y;
    s_slot[t] = g_slots[(b * KSL + ks) * 256 + t];
    __syncthreads();
    int half = t >> 7;
    int cc   = t & 127;
    const float* W = half ? Wqt : Wqs;
    const float rs = 0.08838834764831845f;    // 128^-0.5
    float sc = half ? 0.3f * rs : 0.7f * rs;
    float acc = 0.f;
    const float* sp = &s_slot[half * 128];
#pragma unroll 8
    for (int j = 0; j < 128; ++j) acc += sp[j] * W[j * 128 + cc];
    g_qcat[(b * KSL + ks) * 256 + t] = acc * sc;
}

// ------------------------- 6) logits + softmax(K) + rowsum partials --------
__global__ void __launch_bounds__(256)
logits_softmax_kernel() {
    __shared__ float s_q[8 * 256];
    __shared__ float s_k[32 * 260];
    __shared__ float s_m[32], s_e[32];
    __shared__ float s_a[8][32];
    int t  = threadIdx.x;
    int nc = blockIdx.x, b = blockIdx.y;

#pragma unroll
    for (int i = 0; i < 8; ++i) s_q[t + 256 * i] = g_qcat[b * 2048 + t + 256 * i];
#pragma unroll
    for (int i = 0; i < 8; ++i) {
        int idx = t + 256 * i;                  // float4 units, 0..2047
        int n = idx >> 6, dq = idx & 63;
        float4 v = *reinterpret_cast<const float4*>(
            &g_kcat[(size_t)(b * Nn + nc * 32 + n) * 256 + dq * 4]);
        *reinterpret_cast<float4*>(&s_k[n * 260 + dq * 4]) = v;
    }
    __syncthreads();

    int kk = t >> 5, nl = t & 31;
    const float4* q4 = reinterpret_cast<const float4*>(&s_q[kk * 256]);
    const float4* k4 = reinterpret_cast<const float4*>(&s_k[nl * 260]);
    float acc = 0.f;
#pragma unroll 8
    for (int d = 0; d < 64; ++d) {
        float4 qv = q4[d], kv = k4[d];
        acc += qv.x * kv.x + qv.y * kv.y + qv.z * kv.z + qv.w * kv.w;
    }
    s_a[kk][nl] = acc;
    __syncthreads();

    if (kk == 0) {
        float m = -1e30f;
#pragma unroll
        for (int i = 0; i < 8; ++i) m = fmaxf(m, s_a[i][nl]);
        float e = 0.f;
#pragma unroll
        for (int i = 0; i < 8; ++i) e += expf(s_a[i][nl] - m);
        s_m[nl] = m; s_e[nl] = e;
    }
    __syncthreads();

    float a = expf(acc - s_m[nl]) / s_e[nl];
    g_attn[(size_t)(b * KSL + kk) * Nn + nc * 32 + nl] = a;
    s_a[kk][nl] = a;
    __syncthreads();

    if (nl == 0) {
        float s = 0.f;
#pragma unroll
        for (int i = 0; i < 32; ++i) s += s_a[kk][i];
        g_rowsum_part[(b * KSL + kk) * 128 + nc] = s;
    }
}

// ------------------------- 7) updates stage 1 (partials over n) ------------
__global__ void __launch_bounds__(256)
upd1_kernel() {
    __shared__ float s_a[8][256];
    int t  = threadIdx.x;
    int nc = blockIdx.x, b = blockIdx.y;
#pragma unroll
    for (int i = 0; i < 8; ++i) {
        int idx = t + 256 * i;
        int kk = idx >> 8, nl = idx & 255;
        s_a[kk][nl] = g_attn[(size_t)(b * KSL + kk) * Nn + nc * 256 + nl];
    }
    __syncthreads();
    float acc[8] = {0, 0, 0, 0, 0, 0, 0, 0};
    const float* ip = &g_inputs[(size_t)(b * Nn + nc * 256) * 256 + t];
#pragma unroll 4
    for (int nl = 0; nl < 256; ++nl) {
        float inp = ip[(size_t)nl * 256];
#pragma unroll
        for (int kk = 0; kk < 8; ++kk) acc[kk] += s_a[kk][nl] * inp;
    }
#pragma unroll
    for (int kk = 0; kk < 8; ++kk)
        g_upd_part[((b * 16 + nc) * 8 + kk) * 256 + t] = acc[kk];
}

// ------------------------- 8) fused finalize + GRU + LN + MLP --------------
// grid (4, 32): 2 slots per block, 768 threads. Weights read once per block,
// applied to both slots from registers.
__global__ void __launch_bounds__(768)
gru_mlp_kernel(const float* __restrict__ W_ih, const float* __restrict__ W_hh,
               const float* __restrict__ b_ih, const float* __restrict__ b_hh,
               const float* __restrict__ lng, const float* __restrict__ lnb,
               const float* __restrict__ Wm1, const float* __restrict__ bm1,
               const float* __restrict__ Wm2, const float* __restrict__ bm2) {
    __shared__ float s_x[2][256], s_h[2][256], s_hn[2][256], s_t2[2][512];
    __shared__ float s_gx[2][768], s_gh[2][768];
    __shared__ float wred[16], wred2[16];
    __shared__ float s_irs[2];
    int t  = threadIdx.x;
    int ks0 = blockIdx.x * 2;
    int b   = blockIdx.y;
    int lane = t & 31, w = t >> 5;

    // rowsum reduce: 2 slots x 128 partials; threads 0..255
    {
        float v = 0.f;
        if (t < 256) {
            int sl = t >> 7, i = t & 127;
            v = g_rowsum_part[(b * KSL + ks0 + sl) * 128 + i];
        }
#pragma unroll
        for (int o = 16; o > 0; o >>= 1) v += __shfl_xor_sync(0xffffffffu, v, o);
        if (lane == 0 && w < 8) wred[w] = v;
    }
    __syncthreads();
    if (t < 2) {
        float s = wred[t * 4] + wred[t * 4 + 1] + wred[t * 4 + 2] + wred[t * 4 + 3];
        s_irs[t] = 1.0f / (s + 1e-8f);
    }
    __syncthreads();

    if (t < 512) {
        int sl = t >> 8, d = t & 255;
        float u = 0.f;
#pragma unroll
        for (int ncp = 0; ncp < 16; ++ncp)
            u += g_upd_part[((b * 16 + ncp) * 8 + ks0 + sl) * 256 + d];
        s_x[sl][d] = u * s_irs[sl];
        s_h[sl][d] = g_slots[(b * KSL + ks0 + sl) * 256 + d];
    }
    __syncthreads();

    // gates: thread t = gate column (768). Each weight loaded once, used 2x.
    {
        float bih = b_ih[t], bhh = b_hh[t];
        float gx0 = bih, gx1 = bih, gh0 = bhh, gh1 = bhh;
        gx0 = bih; gx1 = bih; gh0 = bhh; gh1 = bhh;
#pragma unroll 4
        for (int m = 0; m < 256; ++m) {
            float wi = W_ih[m * 768 + t];
            float wh = W_hh[m * 768 + t];
            gx0 += s_x[0][m] * wi;
            gx1 += s_x[1][m] * wi;
            gh0 += s_h[0][m] * wh;
            gh1 += s_h[1][m] * wh;
        }
        s_gx[0][t] = gx0; s_gx[1][t] = gx1;
        s_gh[0][t] = gh0; s_gh[1][t] = gh1;
    }
    __syncthreads();

    // GRU elementwise + LN stats: threads 0..511 (warp covers single slot)
    float h = 0.f;
    int sl = (t < 512) ? (t >> 8) : 0;
    int d  = t & 255;
    if (t < 512) {
        float hprev = s_h[sl][d];
        float r = sigmoidf_(s_gx[sl][d] + s_gh[sl][d]);
        float z = sigmoidf_(s_gx[sl][d + 256] + s_gh[sl][d + 256]);
        float n = tanhf(s_gx[sl][d + 512] + r * s_gh[sl][d + 512]);
        h = (1.0f - z) * n + z * hprev;
    }
    float s1 = h, s2 = h * h;
#pragma unroll
    for (int o = 16; o > 0; o >>= 1) {
        s1 += __shfl_xor_sync(0xffffffffu, s1, o);
        s2 += __shfl_xor_sync(0xffffffffu, s2, o);
    }
    if (lane == 0 && w < 16) { wred[w] = s1; wred2[w] = s2; }
    __syncthreads();
    if (t < 512) {
        float S = 0.f, S2 = 0.f;
#pragma unroll
        for (int i = 0; i < 8; ++i) { S += wred[sl * 8 + i]; S2 += wred2[sl * 8 + i]; }
        float mean = S * (1.0f / 256.0f);
        float var  = S2 * (1.0f / 256.0f) - mean * mean;
        float sn = (h - mean) * rsqrtf(var + 1e-5f) * lng[d] + lnb[d];
        s_hn[sl][d] = h;
        s_x[sl][d]  = sn;
    }
    __syncthreads();

    // MLP layer 1: threads 0..511, one column each for BOTH slots
    if (t < 512) {
        float bb = bm1[t];
        float m0 = bb, m1 = bb;
#pragma unroll 4
        for (int j = 0; j < 256; ++j) {
            float wv = Wm1[j * 512 + t];
            m0 += s_x[0][j] * wv;
            m1 += s_x[1][j] * wv;
        }
        s_t2[0][t] = gelu_exact(m0);
        s_t2[1][t] = gelu_exact(m1);
    }
    __syncthreads();

    // MLP layer 2: threads 0..255, both slots
    if (t < 256) {
        float bb = bm2[t];
        float o0 = bb, o1 = bb;
#pragma unroll 4
        for (int j = 0; j < 512; ++j) {
            float wv = Wm2[j * 256 + t];
            o0 += s_t2[0][j] * wv;
            o1 += s_t2[1][j] * wv;
        }
        g_slots[(b * KSL + ks0) * 256 + t]     = s_hn[0][t] + o0;
        g_slots[(b * KSL + ks0 + 1) * 256 + t] = s_hn[1][t] + o1;
    }
}

// ------------------------- 9) pack outputs ---------------------------------
__global__ void writeout_kernel(float* __restrict__ out) {
    int i = blockIdx.x * 256 + threadIdx.x;   // < 1179648
    const int SZ_SLOTS = Bsz * KSL * DS;      // 65536
    const int SZ_ATTN  = Bsz * KSL * Nn;      // 1048576
    const int SZ_HALF  = Bsz * KSL * DH;      // 32768
    if (i < SZ_SLOTS) {
        out[i] = g_slots[i];
    } else if (i < SZ_SLOTS + SZ_ATTN) {
        out[i] = g_attn[i - SZ_SLOTS];
    } else if (i < SZ_SLOTS + SZ_ATTN + SZ_HALF) {
        int j = i - SZ_SLOTS - SZ_ATTN;
        int bk = j >> 7, d = j & 127;
        out[i] = g_slots[bk * 256 + d];
    } else if (i < SZ_SLOTS + SZ_ATTN + 2 * SZ_HALF) {
        int j = i - SZ_SLOTS - SZ_ATTN - SZ_HALF;
        int bk = j >> 7, d = j & 127;
        out[i] = g_slots[bk * 256 + 128 + d];
    }
}

// ------------------------- launch ------------------------------------------
extern "C" void kernel_launch(void* const* d_in, const int* in_sizes, int n_in,
                              void* d_out, int out_size) {
    const float* features = (const float*)d_in[0];
    const float* Wi1  = (const float*)d_in[1];
    const float* bi1  = (const float*)d_in[2];
    const float* Wi2  = (const float*)d_in[3];
    const float* bi2  = (const float*)d_in[4];
    const float* Wp   = (const float*)d_in[5];
    const float* bp   = (const float*)d_in[6];
    const float* ln_in_g = (const float*)d_in[7];
    const float* ln_in_b = (const float*)d_in[8];
    const float* Wqs  = (const float*)d_in[9];
    const float* Wks  = (const float*)d_in[10];
    const float* Wqt  = (const float*)d_in[11];
    const float* Wkt  = (const float*)d_in[12];
    const float* W_ih = (const float*)d_in[13];
    const float* W_hh = (const float*)d_in[14];
    const float* b_ih = (const float*)d_in[15];
    const float* b_hh = (const float*)d_in[16];
    const float* ln_g = (const float*)d_in[17];
    const float* ln_b = (const float*)d_in[18];
    const float* Wm1  = (const float*)d_in[19];
    const float* bm1  = (const float*)d_in[20];
    const float* Wm2  = (const float*)d_in[21];
    const float* bm2  = (const float*)d_in[22];
    float* out = (float*)d_out;

    cudaFuncSetAttribute(gemm_ln_tc, cudaFuncAttributeMaxDynamicSharedMemorySize,
                         GL_SMEM_BYTES);
    cudaFuncSetAttribute(kproj_tc, cudaFuncAttributeMaxDynamicSharedMemorySize,
                         KP_SMEM_BYTES);

    pool_part_kernel<<<dim3(3, 8, 32), 256>>>(features);
    pool_reduce_kernel<<<dim3(3, 32), 256>>>();
    slots_init1_kernel<<<dim3(2, 32), 256>>>(Wi1, bi1);
    slots_init2_kernel<<<dim3(8, 32), 256>>>(Wi2, bi2);
    gemm_ln_tc<<<1024, 256, GL_SMEM_BYTES>>>(features, Wp, bp, ln_in_g, ln_in_b);
    kproj_tc<<<dim3(1024, 2), 256, KP_SMEM_BYTES>>>(Wks, Wkt);

    for (int it = 0; it < NITER; ++it) {
        qproj_kernel<<<dim3(32, 8), 256>>>(Wqs, Wqt);
        logits_softmax_kernel<<<dim3(128, 32), 256>>>();
        upd1_kernel<<<dim3(16, 32), 256>>>();
        gru_mlp_kernel<<<dim3(4, 32), 768>>>(W_ih, W_hh, b_ih, b_hh,
                                             ln_g, ln_b, Wm1, bm1, Wm2, bm2);
    }
    writeout_kernel<<<4608, 256>>>(out);
}

// round 6
// speedup vs baseline: 1.0002x; 1.0002x over previous
#include <cuda_runtime.h>
#include <math.h>
#include <stdint.h>

#define Bsz   32
#define Nn    4096
#define DIN   768
#define DS    256
#define KSL   8
#define DH    128
#define NITER 3
#define MROWS (Bsz*Nn)   // 131072

// ------------------------- scratch (device globals, no allocs) -------------
__device__ float g_pool_part[Bsz*8*DIN];
__device__ float g_pool[Bsz*DIN];
__device__ float g_t1[Bsz*512];
__device__ float g_slots[Bsz*KSL*DS];
__device__ float g_inputs[MROWS*DS];      // 134 MB
__device__ float g_kcat[MROWS*DS];        // 134 MB
__device__ float g_qcat[Bsz*KSL*DS];
__device__ float g_attn[Bsz*KSL*Nn];
__device__ float g_rowsum_part[Bsz*KSL*128];
__device__ float g_upd_part[Bsz*16*KSL*DS];

__device__ __forceinline__ float gelu_exact(float x) {
    return 0.5f * x * (1.0f + erff(x * 0.70710678118654752f));
}
__device__ __forceinline__ float sigmoidf_(float x) {
    return 1.0f / (1.0f + expf(-x));
}
__device__ __forceinline__ void mma_tf32(float* c, const uint32_t* a,
                                         uint32_t b0, uint32_t b1) {
    asm volatile(
        "mma.sync.aligned.m16n8k8.row.col.f32.tf32.tf32.f32 "
        "{%0,%1,%2,%3}, {%4,%5,%6,%7}, {%8,%9}, {%0,%1,%2,%3};\n"
        : "+f"(c[0]), "+f"(c[1]), "+f"(c[2]), "+f"(c[3])
        : "r"(a[0]), "r"(a[1]), "r"(a[2]), "r"(a[3]), "r"(b0), "r"(b1));
}
__device__ __forceinline__ void cp16(uint32_t* smem_dst, const float* gsrc) {
    unsigned sa = (unsigned)__cvta_generic_to_shared(smem_dst);
    asm volatile("cp.async.cg.shared.global [%0], [%1], 16;\n"
                 :: "r"(sa), "l"(gsrc));
}
__device__ __forceinline__ void cp_commit() {
    asm volatile("cp.async.commit_group;\n");
}
template <int N>
__device__ __forceinline__ void cp_wait() {
    asm volatile("cp.async.wait_group %0;\n" :: "n"(N));
}

extern __shared__ uint32_t g_dyn[];

// ------------------------- 1) feature pooling ------------------------------
__global__ void pool_part_kernel(const float* __restrict__ feat) {
    int d  = blockIdx.x * 256 + threadIdx.x;   // < 768
    int nc = blockIdx.y;
    int b  = blockIdx.z;
    float s = 0.f;
    const float* p = feat + (size_t)(b * Nn + nc * 512) * DIN + d;
    for (int n = 0; n < 512; ++n) s += p[(size_t)n * DIN];
    g_pool_part[(b * 8 + nc) * DIN + d] = s;
}
__global__ void pool_reduce_kernel() {
    int d = blockIdx.x * 256 + threadIdx.x;
    int b = blockIdx.y;
    float s = 0.f;
    for (int i = 0; i < 8; ++i) s += g_pool_part[(b * 8 + i) * DIN + d];
    g_pool[b * DIN + d] = s * (1.0f / (float)Nn);
}

// ------------------------- 2) slot init MLP --------------------------------
__global__ void slots_init1_kernel(const float* __restrict__ Wi1,
                                   const float* __restrict__ bi1) {
    __shared__ float s_pool[DIN];
    int t = threadIdx.x;
    int b = blockIdx.y;
    int j = blockIdx.x * 256 + t;              // < 512
    for (int i = t; i < DIN; i += 256) s_pool[i] = g_pool[b * DIN + i];
    __syncthreads();
    float acc = bi1[j];
    for (int k = 0; k < DIN; ++k) acc += s_pool[k] * Wi1[k * 512 + j];
    g_t1[b * 512 + j] = gelu_exact(acc);
}
__global__ void slots_init2_kernel(const float* __restrict__ Wi2,
                                   const float* __restrict__ bi2) {
    __shared__ float s_t[512];
    int t = threadIdx.x;
    int b = blockIdx.y;
    int j = blockIdx.x * 256 + t;              // < 2048
    s_t[t] = g_t1[b * 512 + t];
    s_t[t + 256] = g_t1[b * 512 + t + 256];
    __syncthreads();
    float acc = bi2[j];
    for (int k = 0; k < 512; ++k) acc += s_t[k] * Wi2[k * 2048 + j];
    g_slots[b * 2048 + j] = acc;
}

// ------------------------- 3) tf32 TC GEMM + fused LN (pipelined) ----------
// inputs = LN(feat @ Wp + bp). BM=128, BN=256, BK=32, 256 threads (8 warps,
// 2x4), warp tile 64x64 (4 mt x 8 nt), 2-stage cp.async.
#define GL_AS_STRIDE 36
#define GL_BS_STRIDE 264
#define GL_AS_SZ (128*GL_AS_STRIDE)     // 4608
#define GL_BS_SZ (32*GL_BS_STRIDE)      // 8448
#define GL_SMEM_BYTES ((2*GL_AS_SZ + 2*GL_BS_SZ)*4)   // 104448

__device__ __forceinline__ void gl_load_stage(
    uint32_t* As, uint32_t* Bs, const float* __restrict__ feat,
    const float* __restrict__ Wp, int bRow, int k0, int t) {
#pragma unroll
    for (int i = 0; i < 4; ++i) {
        int idx = t + 256 * i;                 // 0..1023
        int row = idx >> 3, q = idx & 7;
        cp16(&As[row * GL_AS_STRIDE + q * 4],
             &feat[(size_t)(bRow + row) * DIN + k0 + q * 4]);
    }
#pragma unroll
    for (int i = 0; i < 8; ++i) {
        int idx = t + 256 * i;                 // 0..2047
        int kk = idx >> 6, cq = idx & 63;
        cp16(&Bs[kk * GL_BS_STRIDE + cq * 4],
             &Wp[(size_t)(k0 + kk) * 256 + cq * 4]);
    }
}

__global__ void __launch_bounds__(256)
gemm_ln_tc(const float* __restrict__ feat, const float* __restrict__ Wp,
           const float* __restrict__ bp, const float* __restrict__ lng,
           const float* __restrict__ lnb) {
    uint32_t* AsBuf = g_dyn;
    uint32_t* BsBuf = g_dyn + 2 * GL_AS_SZ;
    __shared__ float s_sum[128][4];
    __shared__ float s_sq[128][4];

    int t = threadIdx.x;
    int lane = t & 31, wid = t >> 5;
    int wr = wid >> 2, wc = wid & 3;    // 2x4 warps: 64 rows x 64 cols each
    int g = lane >> 2, tg = lane & 3;
    int bRow = blockIdx.x * 128;

    float c[4][8][4];
#pragma unroll
    for (int mt = 0; mt < 4; ++mt)
#pragma unroll
        for (int nt = 0; nt < 8; ++nt)
#pragma unroll
            for (int j = 0; j < 4; ++j) c[mt][nt][j] = 0.f;

    gl_load_stage(AsBuf, BsBuf, feat, Wp, bRow, 0, t);
    cp_commit();

    const int NK = DIN / 32;    // 24
    for (int kt = 0; kt < NK; ++kt) {
        int s = kt & 1;
        if (kt + 1 < NK) {
            gl_load_stage(AsBuf + ((kt + 1) & 1) * GL_AS_SZ,
                          BsBuf + ((kt + 1) & 1) * GL_BS_SZ,
                          feat, Wp, bRow, (kt + 1) * 32, t);
            cp_commit();
            cp_wait<1>();
        } else {
            cp_wait<0>();
        }
        __syncthreads();
        uint32_t* As = AsBuf + s * GL_AS_SZ;
        uint32_t* Bs = BsBuf + s * GL_BS_SZ;
#pragma unroll
        for (int ks = 0; ks < 4; ++ks) {
            uint32_t a[4][4];
#pragma unroll
            for (int mt = 0; mt < 4; ++mt) {
                int r = wr * 64 + mt * 16 + g;
                a[mt][0] = As[r * GL_AS_STRIDE + ks * 8 + tg];
                a[mt][1] = As[(r + 8) * GL_AS_STRIDE + ks * 8 + tg];
                a[mt][2] = As[r * GL_AS_STRIDE + ks * 8 + tg + 4];
                a[mt][3] = As[(r + 8) * GL_AS_STRIDE + ks * 8 + tg + 4];
            }
#pragma unroll
            for (int nt = 0; nt < 8; ++nt) {
                int cb = wc * 64 + nt * 8 + g;
                uint32_t b0 = Bs[(ks * 8 + tg) * GL_BS_STRIDE + cb];
                uint32_t b1 = Bs[(ks * 8 + tg + 4) * GL_BS_STRIDE + cb];
#pragma unroll
                for (int mt = 0; mt < 4; ++mt)
                    mma_tf32(c[mt][nt], a[mt], b0, b1);
            }
        }
        __syncthreads();
    }

    // --- epilogue: bias + LN over 256 cols, from register fragments ---
    float2 bpv[8], gv[8], bvv[8];
#pragma unroll
    for (int nt = 0; nt < 8; ++nt) {
        int cb = wc * 64 + nt * 8 + tg * 2;
        bpv[nt] = *reinterpret_cast<const float2*>(&bp[cb]);
        gv[nt]  = *reinterpret_cast<const float2*>(&lng[cb]);
        bvv[nt] = *reinterpret_cast<const float2*>(&lnb[cb]);
    }
    float ls[4][2], lq[4][2];
#pragma unroll
    for (int mt = 0; mt < 4; ++mt)
#pragma unroll
        for (int h = 0; h < 2; ++h) { ls[mt][h] = 0.f; lq[mt][h] = 0.f; }
#pragma unroll
    for (int mt = 0; mt < 4; ++mt)
#pragma unroll
        for (int nt = 0; nt < 8; ++nt) {
            c[mt][nt][0] += bpv[nt].x;
            c[mt][nt][1] += bpv[nt].y;
            c[mt][nt][2] += bpv[nt].x;
            c[mt][nt][3] += bpv[nt].y;
            ls[mt][0] += c[mt][nt][0] + c[mt][nt][1];
            lq[mt][0] += c[mt][nt][0] * c[mt][nt][0] + c[mt][nt][1] * c[mt][nt][1];
            ls[mt][1] += c[mt][nt][2] + c[mt][nt][3];
            lq[mt][1] += c[mt][nt][2] * c[mt][nt][2] + c[mt][nt][3] * c[mt][nt][3];
        }
#pragma unroll
    for (int mt = 0; mt < 4; ++mt)
#pragma unroll
        for (int h = 0; h < 2; ++h) {
            ls[mt][h] += __shfl_xor_sync(0xffffffffu, ls[mt][h], 1);
            ls[mt][h] += __shfl_xor_sync(0xffffffffu, ls[mt][h], 2);
            lq[mt][h] += __shfl_xor_sync(0xffffffffu, lq[mt][h], 1);
            lq[mt][h] += __shfl_xor_sync(0xffffffffu, lq[mt][h], 2);
        }
    if (tg == 0) {
#pragma unroll
        for (int mt = 0; mt < 4; ++mt)
#pragma unroll
            for (int h = 0; h < 2; ++h) {
                int rl = wr * 64 + mt * 16 + h * 8 + g;
                s_sum[rl][wc] = ls[mt][h];
                s_sq[rl][wc]  = lq[mt][h];
            }
    }
    __syncthreads();
    float mean[4][2], inv[4][2];
#pragma unroll
    for (int mt = 0; mt < 4; ++mt)
#pragma unroll
        for (int h = 0; h < 2; ++h) {
            int rl = wr * 64 + mt * 16 + h * 8 + g;
            float S = s_sum[rl][0] + s_sum[rl][1] + s_sum[rl][2] + s_sum[rl][3];
            float Q = s_sq[rl][0] + s_sq[rl][1] + s_sq[rl][2] + s_sq[rl][3];
            float m = S * (1.0f / 256.0f);
            float v = Q * (1.0f / 256.0f) - m * m;
            mean[mt][h] = m;
            inv[mt][h]  = rsqrtf(v + 1e-5f);
        }
#pragma unroll
    for (int mt = 0; mt < 4; ++mt)
#pragma unroll
        for (int nt = 0; nt < 8; ++nt)
#pragma unroll
            for (int h = 0; h < 2; ++h) {
                int rl = wr * 64 + mt * 16 + h * 8 + g;
                size_t row = (size_t)(bRow + rl);
                int cb = wc * 64 + nt * 8 + tg * 2;
                float2 o;
                o.x = (c[mt][nt][h * 2]     - mean[mt][h]) * inv[mt][h] * gv[nt].x + bvv[nt].x;
                o.y = (c[mt][nt][h * 2 + 1] - mean[mt][h]) * inv[mt][h] * gv[nt].y + bvv[nt].y;
                *reinterpret_cast<float2*>(&g_inputs[row * 256 + cb]) = o;
            }
}

// ------------------------- 4) tf32 TC k-projection (pipelined) -------------
// k_cat = [inp_s@Wks | inp_t@Wkt]. grid (1024, 2). BM=128, BN=128, BK=32,
// 256 threads (8 warps 2x4), warp tile 64x32 (4 mt x 4 nt).
#define KP_AS_STRIDE 36
#define KP_BS_STRIDE 136
#define KP_AS_SZ (128*KP_AS_STRIDE)     // 4608
#define KP_BS_SZ (32*KP_BS_STRIDE)      // 4352
#define KP_SMEM_BYTES ((2*KP_AS_SZ + 2*KP_BS_SZ)*4)   // 71680

__device__ __forceinline__ void kp_load_stage(
    uint32_t* As, uint32_t* Bs, const float* __restrict__ W,
    int bRow, int z, int k0, int t) {
#pragma unroll
    for (int i = 0; i < 4; ++i) {
        int idx = t + 256 * i;                 // 0..1023
        int row = idx >> 3, q = idx & 7;
        cp16(&As[row * KP_AS_STRIDE + q * 4],
             &g_inputs[(size_t)(bRow + row) * 256 + z * 128 + k0 + q * 4]);
    }
#pragma unroll
    for (int i = 0; i < 4; ++i) {
        int idx = t + 256 * i;                 // 0..1023
        int kk = idx >> 5, cq = idx & 31;
        cp16(&Bs[kk * KP_BS_STRIDE + cq * 4],
             &W[(size_t)(k0 + kk) * 128 + cq * 4]);
    }
}

__global__ void __launch_bounds__(256)
kproj_tc(const float* __restrict__ Wks, const float* __restrict__ Wkt) {
    uint32_t* AsBuf = g_dyn;
    uint32_t* BsBuf = g_dyn + 2 * KP_AS_SZ;

    int t = threadIdx.x;
    int lane = t & 31, wid = t >> 5;
    int wr = wid >> 2, wc = wid & 3;
    int g = lane >> 2, tg = lane & 3;
    int bRow = blockIdx.x * 128;
    int z = blockIdx.y;
    const float* W = z ? Wkt : Wks;

    float c[4][4][4];
#pragma unroll
    for (int mt = 0; mt < 4; ++mt)
#pragma unroll
        for (int nt = 0; nt < 4; ++nt)
#pragma unroll
            for (int j = 0; j < 4; ++j) c[mt][nt][j] = 0.f;

    kp_load_stage(AsBuf, BsBuf, W, bRow, z, 0, t);
    cp_commit();

    const int NK = 4;   // 128 / 32
    for (int kt = 0; kt < NK; ++kt) {
        int s = kt & 1;
        if (kt + 1 < NK) {
            kp_load_stage(AsBuf + ((kt + 1) & 1) * KP_AS_SZ,
                          BsBuf + ((kt + 1) & 1) * KP_BS_SZ,
                          W, bRow, z, (kt + 1) * 32, t);
            cp_commit();
            cp_wait<1>();
        } else {
            cp_wait<0>();
        }
        __syncthreads();
        uint32_t* As = AsBuf + s * KP_AS_SZ;
        uint32_t* Bs = BsBuf + s * KP_BS_SZ;
#pragma unroll
        for (int ks = 0; ks < 4; ++ks) {
            uint32_t a[4][4];
#pragma unroll
            for (int mt = 0; mt < 4; ++mt) {
                int r = wr * 64 + mt * 16 + g;
                a[mt][0] = As[r * KP_AS_STRIDE + ks * 8 + tg];
                a[mt][1] = As[(r + 8) * KP_AS_STRIDE + ks * 8 + tg];
                a[mt][2] = As[r * KP_AS_STRIDE + ks * 8 + tg + 4];
                a[mt][3] = As[(r + 8) * KP_AS_STRIDE + ks * 8 + tg + 4];
            }
#pragma unroll
            for (int nt = 0; nt < 4; ++nt) {
                int cb = wc * 32 + nt * 8 + g;
                uint32_t b0 = Bs[(ks * 8 + tg) * KP_BS_STRIDE + cb];
                uint32_t b1 = Bs[(ks * 8 + tg + 4) * KP_BS_STRIDE + cb];
#pragma unroll
                for (int mt = 0; mt < 4; ++mt)
                    mma_tf32(c[mt][nt], a[mt], b0, b1);
            }
        }
        __syncthreads();
    }
#pragma unroll
    for (int mt = 0; mt < 4; ++mt)
#pragma unroll
        for (int nt = 0; nt < 4; ++nt)
#pragma unroll
            for (int h = 0; h < 2; ++h) {
                int rl = wr * 64 + mt * 16 + h * 8 + g;
                size_t row = (size_t)(bRow + rl);
                int cb = wc * 32 + nt * 8 + tg * 2;
                float2 o;
                o.x = c[mt][nt][h * 2];
                o.y = c[mt][nt][h * 2 + 1];
                *reinterpret_cast<float2*>(&g_kcat[row * 256 + z * 128 + cb]) = o;
            }
}

// ------------------------- 5) q projection (scales prefolded) --------------
__global__ void qproj_kernel(const float* __restrict__ Wqs,
                             const float* __restrict__ Wqt) {
    __shared__ float s_slot[256];
    int t = threadIdx.x;
    int b = blockIdx.x, ks = blockIdx.y;
    s_slot[t] = g_slots[(b * KSL + ks) * 256 + t];
    __syncthreads();
    int half = t >> 7;
    int cc   = t & 127;
    const float* W = half ? Wqt : Wqs;
    const float rs = 0.08838834764831845f;    // 128^-0.5
    float sc = half ? 0.3f * rs : 0.7f * rs;
    float acc = 0.f;
    const float* sp = &s_slot[half * 128];
#pragma unroll 8
    for (int j = 0; j < 128; ++j) acc += sp[j] * W[j * 128 + cc];
    g_qcat[(b * KSL + ks) * 256 + t] = acc * sc;
}

// ------------------------- 6) logits + softmax(K) + rowsum partials --------
__global__ void __launch_bounds__(256)
logits_softmax_kernel() {
    __shared__ float s_q[8 * 256];
    __shared__ float s_k[32 * 260];
    __shared__ float s_m[32], s_e[32];
    __shared__ float s_a[8][32];
    int t  = threadIdx.x;
    int nc = blockIdx.x, b = blockIdx.y;

#pragma unroll
    for (int i = 0; i < 8; ++i) s_q[t + 256 * i] = g_qcat[b * 2048 + t + 256 * i];
#pragma unroll
    for (int i = 0; i < 8; ++i) {
        int idx = t + 256 * i;                  // float4 units, 0..2047
        int n = idx >> 6, dq = idx & 63;
        float4 v = *reinterpret_cast<const float4*>(
            &g_kcat[(size_t)(b * Nn + nc * 32 + n) * 256 + dq * 4]);
        *reinterpret_cast<float4*>(&s_k[n * 260 + dq * 4]) = v;
    }
    __syncthreads();

    int kk = t >> 5, nl = t & 31;
    const float4* q4 = reinterpret_cast<const float4*>(&s_q[kk * 256]);
    const float4* k4 = reinterpret_cast<const float4*>(&s_k[nl * 260]);
    float acc = 0.f;
#pragma unroll 8
    for (int d = 0; d < 64; ++d) {
        float4 qv = q4[d], kv = k4[d];
        acc += qv.x * kv.x + qv.y * kv.y + qv.z * kv.z + qv.w * kv.w;
    }
    s_a[kk][nl] = acc;
    __syncthreads();

    if (kk == 0) {
        float m = -1e30f;
#pragma unroll
        for (int i = 0; i < 8; ++i) m = fmaxf(m, s_a[i][nl]);
        float e = 0.f;
#pragma unroll
        for (int i = 0; i < 8; ++i) e += expf(s_a[i][nl] - m);
        s_m[nl] = m; s_e[nl] = e;
    }
    __syncthreads();

    float a = expf(acc - s_m[nl]) / s_e[nl];
    g_attn[(size_t)(b * KSL + kk) * Nn + nc * 32 + nl] = a;
    s_a[kk][nl] = a;
    __syncthreads();

    if (nl == 0) {
        float s = 0.f;
#pragma unroll
        for (int i = 0; i < 32; ++i) s += s_a[kk][i];
        g_rowsum_part[(b * KSL + kk) * 128 + nc] = s;
    }
}

// ------------------------- 7) updates stage 1 (partials over n) ------------
__global__ void __launch_bounds__(256)
upd1_kernel() {
    __shared__ float s_a[8][256];
    int t  = threadIdx.x;
    int nc = blockIdx.x, b = blockIdx.y;
#pragma unroll
    for (int i = 0; i < 8; ++i) {
        int idx = t + 256 * i;
        int kk = idx >> 8, nl = idx & 255;
        s_a[kk][nl] = g_attn[(size_t)(b * KSL + kk) * Nn + nc * 256 + nl];
    }
    __syncthreads();
    float acc[8] = {0, 0, 0, 0, 0, 0, 0, 0};
    const float* ip = &g_inputs[(size_t)(b * Nn + nc * 256) * 256 + t];
#pragma unroll 4
    for (int nl = 0; nl < 256; ++nl) {
        float inp = ip[(size_t)nl * 256];
#pragma unroll
        for (int kk = 0; kk < 8; ++kk) acc[kk] += s_a[kk][nl] * inp;
    }
#pragma unroll
    for (int kk = 0; kk < 8; ++kk)
        g_upd_part[((b * 16 + nc) * 8 + kk) * 256 + t] = acc[kk];
}

// ------------------------- 8) fused finalize + GRU + LN + MLP --------------
// grid (4, 32): 2 slots per block, 768 threads. Weights read once per block,
// applied to both slots from registers.
__global__ void __launch_bounds__(768)
gru_mlp_kernel(const float* __restrict__ W_ih, const float* __restrict__ W_hh,
               const float* __restrict__ b_ih, const float* __restrict__ b_hh,
               const float* __restrict__ lng, const float* __restrict__ lnb,
               const float* __restrict__ Wm1, const float* __restrict__ bm1,
               const float* __restrict__ Wm2, const float* __restrict__ bm2) {
    __shared__ float s_x[2][256], s_h[2][256], s_hn[2][256], s_t2[2][512];
    __shared__ float s_gx[2][768], s_gh[2][768];
    __shared__ float wred[16], wred2[16];
    __shared__ float s_irs[2];
    int t  = threadIdx.x;
    int ks0 = blockIdx.x * 2;
    int b   = blockIdx.y;
    int lane = t & 31, w = t >> 5;

    // rowsum reduce: 2 slots x 128 partials; threads 0..255
    {
        float v = 0.f;
        if (t < 256) {
            int sl = t >> 7, i = t & 127;
            v = g_rowsum_part[(b * KSL + ks0 + sl) * 128 + i];
        }
#pragma unroll
        for (int o = 16; o > 0; o >>= 1) v += __shfl_xor_sync(0xffffffffu, v, o);
        if (lane == 0 && w < 8) wred[w] = v;
    }
    __syncthreads();
    if (t < 2) {
        float s = wred[t * 4] + wred[t * 4 + 1] + wred[t * 4 + 2] + wred[t * 4 + 3];
        s_irs[t] = 1.0f / (s + 1e-8f);
    }
    __syncthreads();

    if (t < 512) {
        int sl = t >> 8, d = t & 255;
        float u = 0.f;
#pragma unroll
        for (int ncp = 0; ncp < 16; ++ncp)
            u += g_upd_part[((b * 16 + ncp) * 8 + ks0 + sl) * 256 + d];
        s_x[sl][d] = u * s_irs[sl];
        s_h[sl][d] = g_slots[(b * KSL + ks0 + sl) * 256 + d];
    }
    __syncthreads();

    // gates: thread t = gate column (768). Each weight loaded once, used 2x.
    {
        float bih = b_ih[t], bhh = b_hh[t];
        float gx0 = bih, gx1 = bih, gh0 = bhh, gh1 = bhh;
        gx0 = bih; gx1 = bih; gh0 = bhh; gh1 = bhh;
#pragma unroll 4
        for (int m = 0; m < 256; ++m) {
            float wi = W_ih[m * 768 + t];
            float wh = W_hh[m * 768 + t];
            gx0 += s_x[0][m] * wi;
            gx1 += s_x[1][m] * wi;
            gh0 += s_h[0][m] * wh;
            gh1 += s_h[1][m] * wh;
        }
        s_gx[0][t] = gx0; s_gx[1][t] = gx1;
        s_gh[0][t] = gh0; s_gh[1][t] = gh1;
    }
    __syncthreads();

    // GRU elementwise + LN stats: threads 0..511 (warp covers single slot)
    float h = 0.f;
    int sl = (t < 512) ? (t >> 8) : 0;
    int d  = t & 255;
    if (t < 512) {
        float hprev = s_h[sl][d];
        float r = sigmoidf_(s_gx[sl][d] + s_gh[sl][d]);
        float z = sigmoidf_(s_gx[sl][d + 256] + s_gh[sl][d + 256]);
        float n = tanhf(s_gx[sl][d + 512] + r * s_gh[sl][d + 512]);
        h = (1.0f - z) * n + z * hprev;
    }
    float s1 = h, s2 = h * h;
#pragma unroll
    for (int o = 16; o > 0; o >>= 1) {
        s1 += __shfl_xor_sync(0xffffffffu, s1, o);
        s2 += __shfl_xor_sync(0xffffffffu, s2, o);
    }
    if (lane == 0 && w < 16) { wred[w] = s1; wred2[w] = s2; }
    __syncthreads();
    if (t < 512) {
        float S = 0.f, S2 = 0.f;
#pragma unroll
        for (int i = 0; i < 8; ++i) { S += wred[sl * 8 + i]; S2 += wred2[sl * 8 + i]; }
        float mean = S * (1.0f / 256.0f);
        float var  = S2 * (1.0f / 256.0f) - mean * mean;
        float sn = (h - mean) * rsqrtf(var + 1e-5f) * lng[d] + lnb[d];
        s_hn[sl][d] = h;
        s_x[sl][d]  = sn;
    }
    __syncthreads();

    // MLP layer 1: threads 0..511, one column each for BOTH slots
    if (t < 512) {
        float bb = bm1[t];
        float m0 = bb, m1 = bb;
#pragma unroll 4
        for (int j = 0; j < 256; ++j) {
            float wv = Wm1[j * 512 + t];
            m0 += s_x[0][j] * wv;
            m1 += s_x[1][j] * wv;
        }
        s_t2[0][t] = gelu_exact(m0);
        s_t2[1][t] = gelu_exact(m1);
    }
    __syncthreads();

    // MLP layer 2: threads 0..255, both slots
    if (t < 256) {
        float bb = bm2[t];
        float o0 = bb, o1 = bb;
#pragma unroll 4
        for (int j = 0; j < 512; ++j) {
            float wv = Wm2[j * 256 + t];
            o0 += s_t2[0][j] * wv;
            o1 += s_t2[1][j] * wv;
        }
        g_slots[(b * KSL + ks0) * 256 + t]     = s_hn[0][t] + o0;
        g_slots[(b * KSL + ks0 + 1) * 256 + t] = s_hn[1][t] + o1;
    }
}

// ------------------------- 9) pack outputs ---------------------------------
__global__ void writeout_kernel(float* __restrict__ out) {
    int i = blockIdx.x * 256 + threadIdx.x;   // < 1179648
    const int SZ_SLOTS = Bsz * KSL * DS;      // 65536
    const int SZ_ATTN  = Bsz * KSL * Nn;      // 1048576
    const int SZ_HALF  = Bsz * KSL * DH;      // 32768
    if (i < SZ_SLOTS) {
        out[i] = g_slots[i];
    } else if (i < SZ_SLOTS + SZ_ATTN) {
        out[i] = g_attn[i - SZ_SLOTS];
    } else if (i < SZ_SLOTS + SZ_ATTN + SZ_HALF) {
        int j = i - SZ_SLOTS - SZ_ATTN;
        int bk = j >> 7, d = j & 127;
        out[i] = g_slots[bk * 256 + d];
    } else if (i < SZ_SLOTS + SZ_ATTN + 2 * SZ_HALF) {
        int j = i - SZ_SLOTS - SZ_ATTN - SZ_HALF;
        int bk = j >> 7, d = j & 127;
        out[i] = g_slots[bk * 256 + 128 + d];
    }
}

// ------------------------- launch ------------------------------------------
extern "C" void kernel_launch(void* const* d_in, const int* in_sizes, int n_in,
                              void* d_out, int out_size) {
    const float* features = (const float*)d_in[0];
    const float* Wi1  = (const float*)d_in[1];
    const float* bi1  = (const float*)d_in[2];
    const float* Wi2  = (const float*)d_in[3];
    const float* bi2  = (const float*)d_in[4];
    const float* Wp   = (const float*)d_in[5];
    const float* bp   = (const float*)d_in[6];
    const float* ln_in_g = (const float*)d_in[7];
    const float* ln_in_b = (const float*)d_in[8];
    const float* Wqs  = (const float*)d_in[9];
    const float* Wks  = (const float*)d_in[10];
    const float* Wqt  = (const float*)d_in[11];
    const float* Wkt  = (const float*)d_in[12];
    const float* W_ih = (const float*)d_in[13];
    const float* W_hh = (const float*)d_in[14];
    const float* b_ih = (const float*)d_in[15];
    const float* b_hh = (const float*)d_in[16];
    const float* ln_g = (const float*)d_in[17];
    const float* ln_b = (const float*)d_in[18];
    const float* Wm1  = (const float*)d_in[19];
    const float* bm1  = (const float*)d_in[20];
    const float* Wm2  = (const float*)d_in[21];
    const float* bm2  = (const float*)d_in[22];
    float* out = (float*)d_out;

    cudaFuncSetAttribute(gemm_ln_tc, cudaFuncAttributeMaxDynamicSharedMemorySize,
                         GL_SMEM_BYTES);
    cudaFuncSetAttribute(kproj_tc, cudaFuncAttributeMaxDynamicSharedMemorySize,
                         KP_SMEM_BYTES);

    pool_part_kernel<<<dim3(3, 8, 32), 256>>>(features);
    pool_reduce_kernel<<<dim3(3, 32), 256>>>();
    slots_init1_kernel<<<dim3(2, 32), 256>>>(Wi1, bi1);
    slots_init2_kernel<<<dim3(8, 32), 256>>>(Wi2, bi2);
    gemm_ln_tc<<<1024, 256, GL_SMEM_BYTES>>>(features, Wp, bp, ln_in_g, ln_in_b);
    kproj_tc<<<dim3(1024, 2), 256, KP_SMEM_BYTES>>>(Wks, Wkt);

    for (int it = 0; it < NITER; ++it) {
        qproj_kernel<<<dim3(32, 8), 256>>>(Wqs, Wqt);
        logits_softmax_kernel<<<dim3(128, 32), 256>>>();
        upd1_kernel<<<dim3(16, 32), 256>>>();
        gru_mlp_kernel<<<dim3(4, 32), 768>>>(W_ih, W_hh, b_ih, b_hh,
                                             ln_g, ln_b, Wm1, bm1, Wm2, bm2);
    }
    writeout_kernel<<<4608, 256>>>(out);
}

// round 7
// speedup vs baseline: 1.0019x; 1.0017x over previous
#include <cuda_runtime.h>
#include <math.h>
#include <stdint.h>

#define Bsz   32
#define Nn    4096
#define DIN   768
#define DS    256
#define KSL   8
#define DH    128
#define NITER 3
#define MROWS (Bsz*Nn)   // 131072

// ------------------------- scratch (device globals, no allocs) -------------
__device__ float g_pool_part[Bsz*8*DIN];
__device__ float g_pool[Bsz*DIN];
__device__ float g_t1[Bsz*512];
__device__ float g_slots[Bsz*KSL*DS];
__device__ float g_inputs[MROWS*DS];      // 134 MB
__device__ float g_kcat[MROWS*DS];        // 134 MB
__device__ float g_qcat[Bsz*KSL*DS];
__device__ float g_attn[Bsz*KSL*Nn];
__device__ float g_rowsum_part[Bsz*KSL*128];
__device__ float g_upd_part[Bsz*16*KSL*DS];

__device__ __forceinline__ float gelu_exact(float x) {
    return 0.5f * x * (1.0f + erff(x * 0.70710678118654752f));
}
__device__ __forceinline__ float sigmoidf_(float x) {
    return 1.0f / (1.0f + expf(-x));
}
__device__ __forceinline__ void mma_tf32(float* c, const uint32_t* a,
                                         uint32_t b0, uint32_t b1) {
    asm volatile(
        "mma.sync.aligned.m16n8k8.row.col.f32.tf32.tf32.f32 "
        "{%0,%1,%2,%3}, {%4,%5,%6,%7}, {%8,%9}, {%0,%1,%2,%3};\n"
        : "+f"(c[0]), "+f"(c[1]), "+f"(c[2]), "+f"(c[3])
        : "r"(a[0]), "r"(a[1]), "r"(a[2]), "r"(a[3]), "r"(b0), "r"(b1));
}
__device__ __forceinline__ void cp16(uint32_t* smem_dst, const float* gsrc) {
    unsigned sa = (unsigned)__cvta_generic_to_shared(smem_dst);
    asm volatile("cp.async.cg.shared.global [%0], [%1], 16;\n"
                 :: "r"(sa), "l"(gsrc));
}
__device__ __forceinline__ void cp_commit() {
    asm volatile("cp.async.commit_group;\n");
}
template <int N>
__device__ __forceinline__ void cp_wait() {
    asm volatile("cp.async.wait_group %0;\n" :: "n"(N));
}

extern __shared__ uint32_t g_dyn[];

// ------------------------- 1) feature pooling ------------------------------
__global__ void pool_part_kernel(const float* __restrict__ feat) {
    int d  = blockIdx.x * 256 + threadIdx.x;   // < 768
    int nc = blockIdx.y;
    int b  = blockIdx.z;
    float s = 0.f;
    const float* p = feat + (size_t)(b * Nn + nc * 512) * DIN + d;
    for (int n = 0; n < 512; ++n) s += p[(size_t)n * DIN];
    g_pool_part[(b * 8 + nc) * DIN + d] = s;
}
__global__ void pool_reduce_kernel() {
    int d = blockIdx.x * 256 + threadIdx.x;
    int b = blockIdx.y;
    float s = 0.f;
    for (int i = 0; i < 8; ++i) s += g_pool_part[(b * 8 + i) * DIN + d];
    g_pool[b * DIN + d] = s * (1.0f / (float)Nn);
}

// ------------------------- 2) slot init MLP --------------------------------
__global__ void slots_init1_kernel(const float* __restrict__ Wi1,
                                   const float* __restrict__ bi1) {
    __shared__ float s_pool[DIN];
    int t = threadIdx.x;
    int b = blockIdx.y;
    int j = blockIdx.x * 256 + t;              // < 512
    for (int i = t; i < DIN; i += 256) s_pool[i] = g_pool[b * DIN + i];
    __syncthreads();
    float acc = bi1[j];
    for (int k = 0; k < DIN; ++k) acc += s_pool[k] * Wi1[k * 512 + j];
    g_t1[b * 512 + j] = gelu_exact(acc);
}
__global__ void slots_init2_kernel(const float* __restrict__ Wi2,
                                   const float* __restrict__ bi2) {
    __shared__ float s_t[512];
    int t = threadIdx.x;
    int b = blockIdx.y;
    int j = blockIdx.x * 256 + t;              // < 2048
    s_t[t] = g_t1[b * 512 + t];
    s_t[t + 256] = g_t1[b * 512 + t + 256];
    __syncthreads();
    float acc = bi2[j];
    for (int k = 0; k < 512; ++k) acc += s_t[k] * Wi2[k * 2048 + j];
    g_slots[b * 2048 + j] = acc;
}

// ------------------------- 3) tf32 TC GEMM + fused LN (pipelined) ----------
// inputs = LN(feat @ Wp + bp). BM=128, BN=256, BK=32, 256 threads (8 warps,
// 2x4), warp tile 64x64 (4 mt x 8 nt), 2-stage cp.async.
#define GL_AS_STRIDE 36
#define GL_BS_STRIDE 264
#define GL_AS_SZ (128*GL_AS_STRIDE)     // 4608
#define GL_BS_SZ (32*GL_BS_STRIDE)      // 8448
#define GL_SMEM_BYTES ((2*GL_AS_SZ + 2*GL_BS_SZ)*4)   // 104448

__device__ __forceinline__ void gl_load_stage(
    uint32_t* As, uint32_t* Bs, const float* __restrict__ feat,
    const float* __restrict__ Wp, int bRow, int k0, int t) {
#pragma unroll
    for (int i = 0; i < 4; ++i) {
        int idx = t + 256 * i;                 // 0..1023
        int row = idx >> 3, q = idx & 7;
        cp16(&As[row * GL_AS_STRIDE + q * 4],
             &feat[(size_t)(bRow + row) * DIN + k0 + q * 4]);
    }
#pragma unroll
    for (int i = 0; i < 8; ++i) {
        int idx = t + 256 * i;                 // 0..2047
        int kk = idx >> 6, cq = idx & 63;
        cp16(&Bs[kk * GL_BS_STRIDE + cq * 4],
             &Wp[(size_t)(k0 + kk) * 256 + cq * 4]);
    }
}

__global__ void __launch_bounds__(256)
gemm_ln_tc(const float* __restrict__ feat, const float* __restrict__ Wp,
           const float* __restrict__ bp, const float* __restrict__ lng,
           const float* __restrict__ lnb) {
    uint32_t* AsBuf = g_dyn;
    uint32_t* BsBuf = g_dyn + 2 * GL_AS_SZ;
    __shared__ float s_sum[128][4];
    __shared__ float s_sq[128][4];

    int t = threadIdx.x;
    int lane = t & 31, wid = t >> 5;
    int wr = wid >> 2, wc = wid & 3;    // 2x4 warps: 64 rows x 64 cols each
    int g = lane >> 2, tg = lane & 3;
    int bRow = blockIdx.x * 128;

    float c[4][8][4];
#pragma unroll
    for (int mt = 0; mt < 4; ++mt)
#pragma unroll
        for (int nt = 0; nt < 8; ++nt)
#pragma unroll
            for (int j = 0; j < 4; ++j) c[mt][nt][j] = 0.f;

    gl_load_stage(AsBuf, BsBuf, feat, Wp, bRow, 0, t);
    cp_commit();

    const int NK = DIN / 32;    // 24
    for (int kt = 0; kt < NK; ++kt) {
        int s = kt & 1;
        if (kt + 1 < NK) {
            gl_load_stage(AsBuf + ((kt + 1) & 1) * GL_AS_SZ,
                          BsBuf + ((kt + 1) & 1) * GL_BS_SZ,
                          feat, Wp, bRow, (kt + 1) * 32, t);
            cp_commit();
            cp_wait<1>();
        } else {
            cp_wait<0>();
        }
        __syncthreads();
        uint32_t* As = AsBuf + s * GL_AS_SZ;
        uint32_t* Bs = BsBuf + s * GL_BS_SZ;
#pragma unroll
        for (int ks = 0; ks < 4; ++ks) {
            uint32_t a[4][4];
#pragma unroll
            for (int mt = 0; mt < 4; ++mt) {
                int r = wr * 64 + mt * 16 + g;
                a[mt][0] = As[r * GL_AS_STRIDE + ks * 8 + tg];
                a[mt][1] = As[(r + 8) * GL_AS_STRIDE + ks * 8 + tg];
                a[mt][2] = As[r * GL_AS_STRIDE + ks * 8 + tg + 4];
                a[mt][3] = As[(r + 8) * GL_AS_STRIDE + ks * 8 + tg + 4];
            }
#pragma unroll
            for (int nt = 0; nt < 8; ++nt) {
                int cb = wc * 64 + nt * 8 + g;
                uint32_t b0 = Bs[(ks * 8 + tg) * GL_BS_STRIDE + cb];
                uint32_t b1 = Bs[(ks * 8 + tg + 4) * GL_BS_STRIDE + cb];
#pragma unroll
                for (int mt = 0; mt < 4; ++mt)
                    mma_tf32(c[mt][nt], a[mt], b0, b1);
            }
        }
        __syncthreads();
    }

    // --- epilogue: bias + LN over 256 cols, from register fragments ---
    float2 bpv[8], gv[8], bvv[8];
#pragma unroll
    for (int nt = 0; nt < 8; ++nt) {
        int cb = wc * 64 + nt * 8 + tg * 2;
        bpv[nt] = *reinterpret_cast<const float2*>(&bp[cb]);
        gv[nt]  = *reinterpret_cast<const float2*>(&lng[cb]);
        bvv[nt] = *reinterpret_cast<const float2*>(&lnb[cb]);
    }
    float ls[4][2], lq[4][2];
#pragma unroll
    for (int mt = 0; mt < 4; ++mt)
#pragma unroll
        for (int h = 0; h < 2; ++h) { ls[mt][h] = 0.f; lq[mt][h] = 0.f; }
#pragma unroll
    for (int mt = 0; mt < 4; ++mt)
#pragma unroll
        for (int nt = 0; nt < 8; ++nt) {
            c[mt][nt][0] += bpv[nt].x;
            c[mt][nt][1] += bpv[nt].y;
            c[mt][nt][2] += bpv[nt].x;
            c[mt][nt][3] += bpv[nt].y;
            ls[mt][0] += c[mt][nt][0] + c[mt][nt][1];
            lq[mt][0] += c[mt][nt][0] * c[mt][nt][0] + c[mt][nt][1] * c[mt][nt][1];
            ls[mt][1] += c[mt][nt][2] + c[mt][nt][3];
            lq[mt][1] += c[mt][nt][2] * c[mt][nt][2] + c[mt][nt][3] * c[mt][nt][3];
        }
#pragma unroll
    for (int mt = 0; mt < 4; ++mt)
#pragma unroll
        for (int h = 0; h < 2; ++h) {
            ls[mt][h] += __shfl_xor_sync(0xffffffffu, ls[mt][h], 1);
            ls[mt][h] += __shfl_xor_sync(0xffffffffu, ls[mt][h], 2);
            lq[mt][h] += __shfl_xor_sync(0xffffffffu, lq[mt][h], 1);
            lq[mt][h] += __shfl_xor_sync(0xffffffffu, lq[mt][h], 2);
        }
    if (tg == 0) {
#pragma unroll
        for (int mt = 0; mt < 4; ++mt)
#pragma unroll
            for (int h = 0; h < 2; ++h) {
                int rl = wr * 64 + mt * 16 + h * 8 + g;
                s_sum[rl][wc] = ls[mt][h];
                s_sq[rl][wc]  = lq[mt][h];
            }
    }
    __syncthreads();
    float mean[4][2], inv[4][2];
#pragma unroll
    for (int mt = 0; mt < 4; ++mt)
#pragma unroll
        for (int h = 0; h < 2; ++h) {
            int rl = wr * 64 + mt * 16 + h * 8 + g;
            float S = s_sum[rl][0] + s_sum[rl][1] + s_sum[rl][2] + s_sum[rl][3];
            float Q = s_sq[rl][0] + s_sq[rl][1] + s_sq[rl][2] + s_sq[rl][3];
            float m = S * (1.0f / 256.0f);
            float v = Q * (1.0f / 256.0f) - m * m;
            mean[mt][h] = m;
            inv[mt][h]  = rsqrtf(v + 1e-5f);
        }
#pragma unroll
    for (int mt = 0; mt < 4; ++mt)
#pragma unroll
        for (int nt = 0; nt < 8; ++nt)
#pragma unroll
            for (int h = 0; h < 2; ++h) {
                int rl = wr * 64 + mt * 16 + h * 8 + g;
                size_t row = (size_t)(bRow + rl);
                int cb = wc * 64 + nt * 8 + tg * 2;
                float2 o;
                o.x = (c[mt][nt][h * 2]     - mean[mt][h]) * inv[mt][h] * gv[nt].x + bvv[nt].x;
                o.y = (c[mt][nt][h * 2 + 1] - mean[mt][h]) * inv[mt][h] * gv[nt].y + bvv[nt].y;
                *reinterpret_cast<float2*>(&g_inputs[row * 256 + cb]) = o;
            }
}

// ------------------------- 4) tf32 TC k-projection (pipelined) -------------
// k_cat = [inp_s@Wks | inp_t@Wkt]. grid (1024, 2). BM=128, BN=128, BK=32,
// 256 threads (8 warps 2x4), warp tile 64x32 (4 mt x 4 nt).
#define KP_AS_STRIDE 36
#define KP_BS_STRIDE 136
#define KP_AS_SZ (128*KP_AS_STRIDE)     // 4608
#define KP_BS_SZ (32*KP_BS_STRIDE)      // 4352
#define KP_SMEM_BYTES ((2*KP_AS_SZ + 2*KP_BS_SZ)*4)   // 71680

__device__ __forceinline__ void kp_load_stage(
    uint32_t* As, uint32_t* Bs, const float* __restrict__ W,
    int bRow, int z, int k0, int t) {
#pragma unroll
    for (int i = 0; i < 4; ++i) {
        int idx = t + 256 * i;                 // 0..1023
        int row = idx >> 3, q = idx & 7;
        cp16(&As[row * KP_AS_STRIDE + q * 4],
             &g_inputs[(size_t)(bRow + row) * 256 + z * 128 + k0 + q * 4]);
    }
#pragma unroll
    for (int i = 0; i < 4; ++i) {
        int idx = t + 256 * i;                 // 0..1023
        int kk = idx >> 5, cq = idx & 31;
        cp16(&Bs[kk * KP_BS_STRIDE + cq * 4],
             &W[(size_t)(k0 + kk) * 128 + cq * 4]);
    }
}

__global__ void __launch_bounds__(256)
kproj_tc(const float* __restrict__ Wks, const float* __restrict__ Wkt) {
    uint32_t* AsBuf = g_dyn;
    uint32_t* BsBuf = g_dyn + 2 * KP_AS_SZ;

    int t = threadIdx.x;
    int lane = t & 31, wid = t >> 5;
    int wr = wid >> 2, wc = wid & 3;
    int g = lane >> 2, tg = lane & 3;
    int bRow = blockIdx.x * 128;
    int z = blockIdx.y;
    const float* W = z ? Wkt : Wks;

    float c[4][4][4];
#pragma unroll
    for (int mt = 0; mt < 4; ++mt)
#pragma unroll
        for (int nt = 0; nt < 4; ++nt)
#pragma unroll
            for (int j = 0; j < 4; ++j) c[mt][nt][j] = 0.f;

    kp_load_stage(AsBuf, BsBuf, W, bRow, z, 0, t);
    cp_commit();

    const int NK = 4;   // 128 / 32
    for (int kt = 0; kt < NK; ++kt) {
        int s = kt & 1;
        if (kt + 1 < NK) {
            kp_load_stage(AsBuf + ((kt + 1) & 1) * KP_AS_SZ,
                          BsBuf + ((kt + 1) & 1) * KP_BS_SZ,
                          W, bRow, z, (kt + 1) * 32, t);
            cp_commit();
            cp_wait<1>();
        } else {
            cp_wait<0>();
        }
        __syncthreads();
        uint32_t* As = AsBuf + s * KP_AS_SZ;
        uint32_t* Bs = BsBuf + s * KP_BS_SZ;
#pragma unroll
        for (int ks = 0; ks < 4; ++ks) {
            uint32_t a[4][4];
#pragma unroll
            for (int mt = 0; mt < 4; ++mt) {
                int r = wr * 64 + mt * 16 + g;
                a[mt][0] = As[r * KP_AS_STRIDE + ks * 8 + tg];
                a[mt][1] = As[(r + 8) * KP_AS_STRIDE + ks * 8 + tg];
                a[mt][2] = As[r * KP_AS_STRIDE + ks * 8 + tg + 4];
                a[mt][3] = As[(r + 8) * KP_AS_STRIDE + ks * 8 + tg + 4];
            }
#pragma unroll
            for (int nt = 0; nt < 4; ++nt) {
                int cb = wc * 32 + nt * 8 + g;
                uint32_t b0 = Bs[(ks * 8 + tg) * KP_BS_STRIDE + cb];
                uint32_t b1 = Bs[(ks * 8 + tg + 4) * KP_BS_STRIDE + cb];
#pragma unroll
                for (int mt = 0; mt < 4; ++mt)
                    mma_tf32(c[mt][nt], a[mt], b0, b1);
            }
        }
        __syncthreads();
    }
#pragma unroll
    for (int mt = 0; mt < 4; ++mt)
#pragma unroll
        for (int nt = 0; nt < 4; ++nt)
#pragma unroll
            for (int h = 0; h < 2; ++h) {
                int rl = wr * 64 + mt * 16 + h * 8 + g;
                size_t row = (size_t)(bRow + rl);
                int cb = wc * 32 + nt * 8 + tg * 2;
                float2 o;
                o.x = c[mt][nt][h * 2];
                o.y = c[mt][nt][h * 2 + 1];
                *reinterpret_cast<float2*>(&g_kcat[row * 256 + z * 128 + cb]) = o;
            }
}

// ------------------------- 5) q projection (scales prefolded) --------------
__global__ void qproj_kernel(const float* __restrict__ Wqs,
                             const float* __restrict__ Wqt) {
    __shared__ float s_slot[256];
    int t = threadIdx.x;
    int b = blockIdx.x, ks = blockIdx.y;
    s_slot[t] = g_slots[(b * KSL + ks) * 256 + t];
    __syncthreads();
    int half = t >> 7;
    int cc   = t & 127;
    const float* W = half ? Wqt : Wqs;
    const float rs = 0.08838834764831845f;    // 128^-0.5
    float sc = half ? 0.3f * rs : 0.7f * rs;
    float acc = 0.f;
    const float* sp = &s_slot[half * 128];
#pragma unroll 8
    for (int j = 0; j < 128; ++j) acc += sp[j] * W[j * 128 + cc];
    g_qcat[(b * KSL + ks) * 256 + t] = acc * sc;
}

// ------------------------- 6) logits + softmax(K) + rowsum partials --------
__global__ void __launch_bounds__(256)
logits_softmax_kernel() {
    __shared__ float s_q[8 * 256];
    __shared__ float s_k[32 * 260];
    __shared__ float s_m[32], s_e[32];
    __shared__ float s_a[8][32];
    int t  = threadIdx.x;
    int nc = blockIdx.x, b = blockIdx.y;

#pragma unroll
    for (int i = 0; i < 8; ++i) s_q[t + 256 * i] = g_qcat[b * 2048 + t + 256 * i];
#pragma unroll
    for (int i = 0; i < 8; ++i) {
        int idx = t + 256 * i;                  // float4 units, 0..2047
        int n = idx >> 6, dq = idx & 63;
        float4 v = *reinterpret_cast<const float4*>(
            &g_kcat[(size_t)(b * Nn + nc * 32 + n) * 256 + dq * 4]);
        *reinterpret_cast<float4*>(&s_k[n * 260 + dq * 4]) = v;
    }
    __syncthreads();

    int kk = t >> 5, nl = t & 31;
    const float4* q4 = reinterpret_cast<const float4*>(&s_q[kk * 256]);
    const float4* k4 = reinterpret_cast<const float4*>(&s_k[nl * 260]);
    float acc = 0.f;
#pragma unroll 8
    for (int d = 0; d < 64; ++d) {
        float4 qv = q4[d], kv = k4[d];
        acc += qv.x * kv.x + qv.y * kv.y + qv.z * kv.z + qv.w * kv.w;
    }
    s_a[kk][nl] = acc;
    __syncthreads();

    if (kk == 0) {
        float m = -1e30f;
#pragma unroll
        for (int i = 0; i < 8; ++i) m = fmaxf(m, s_a[i][nl]);
        float e = 0.f;
#pragma unroll
        for (int i = 0; i < 8; ++i) e += expf(s_a[i][nl] - m);
        s_m[nl] = m; s_e[nl] = e;
    }
    __syncthreads();

    float a = expf(acc - s_m[nl]) / s_e[nl];
    g_attn[(size_t)(b * KSL + kk) * Nn + nc * 32 + nl] = a;
    s_a[kk][nl] = a;
    __syncthreads();

    if (nl == 0) {
        float s = 0.f;
#pragma unroll
        for (int i = 0; i < 32; ++i) s += s_a[kk][i];
        g_rowsum_part[(b * KSL + kk) * 128 + nc] = s;
    }
}

// ------------------------- 7) updates stage 1 (partials over n) ------------
__global__ void __launch_bounds__(256)
upd1_kernel() {
    __shared__ float s_a[8][256];
    int t  = threadIdx.x;
    int nc = blockIdx.x, b = blockIdx.y;
#pragma unroll
    for (int i = 0; i < 8; ++i) {
        int idx = t + 256 * i;
        int kk = idx >> 8, nl = idx & 255;
        s_a[kk][nl] = g_attn[(size_t)(b * KSL + kk) * Nn + nc * 256 + nl];
    }
    __syncthreads();
    float acc[8] = {0, 0, 0, 0, 0, 0, 0, 0};
    const float* ip = &g_inputs[(size_t)(b * Nn + nc * 256) * 256 + t];
#pragma unroll 4
    for (int nl = 0; nl < 256; ++nl) {
        float inp = ip[(size_t)nl * 256];
#pragma unroll
        for (int kk = 0; kk < 8; ++kk) acc[kk] += s_a[kk][nl] * inp;
    }
#pragma unroll
    for (int kk = 0; kk < 8; ++kk)
        g_upd_part[((b * 16 + nc) * 8 + kk) * 256 + t] = acc[kk];
}

// ------------------------- 8) fused finalize + GRU + LN + MLP --------------
// grid (4, 32): 2 slots per block, 768 threads. Weights read once per block,
// applied to both slots from registers.
__global__ void __launch_bounds__(768)
gru_mlp_kernel(const float* __restrict__ W_ih, const float* __restrict__ W_hh,
               const float* __restrict__ b_ih, const float* __restrict__ b_hh,
               const float* __restrict__ lng, const float* __restrict__ lnb,
               const float* __restrict__ Wm1, const float* __restrict__ bm1,
               const float* __restrict__ Wm2, const float* __restrict__ bm2) {
    __shared__ float s_x[2][256], s_h[2][256], s_hn[2][256], s_t2[2][512];
    __shared__ float s_gx[2][768], s_gh[2][768];
    __shared__ float wred[16], wred2[16];
    __shared__ float s_irs[2];
    int t  = threadIdx.x;
    int ks0 = blockIdx.x * 2;
    int b   = blockIdx.y;
    int lane = t & 31, w = t >> 5;

    // rowsum reduce: 2 slots x 128 partials; threads 0..255
    {
        float v = 0.f;
        if (t < 256) {
            int sl = t >> 7, i = t & 127;
            v = g_rowsum_part[(b * KSL + ks0 + sl) * 128 + i];
        }
#pragma unroll
        for (int o = 16; o > 0; o >>= 1) v += __shfl_xor_sync(0xffffffffu, v, o);
        if (lane == 0 && w < 8) wred[w] = v;
    }
    __syncthreads();
    if (t < 2) {
        float s = wred[t * 4] + wred[t * 4 + 1] + wred[t * 4 + 2] + wred[t * 4 + 3];
        s_irs[t] = 1.0f / (s + 1e-8f);
    }
    __syncthreads();

    if (t < 512) {
        int sl = t >> 8, d = t & 255;
        float u = 0.f;
#pragma unroll
        for (int ncp = 0; ncp < 16; ++ncp)
            u += g_upd_part[((b * 16 + ncp) * 8 + ks0 + sl) * 256 + d];
        s_x[sl][d] = u * s_irs[sl];
        s_h[sl][d] = g_slots[(b * KSL + ks0 + sl) * 256 + d];
    }
    __syncthreads();

    // gates: thread t = gate column (768). Each weight loaded once, used 2x.
    {
        float bih = b_ih[t], bhh = b_hh[t];
        float gx0 = bih, gx1 = bih, gh0 = bhh, gh1 = bhh;
        gx0 = bih; gx1 = bih; gh0 = bhh; gh1 = bhh;
#pragma unroll 4
        for (int m = 0; m < 256; ++m) {
            float wi = W_ih[m * 768 + t];
            float wh = W_hh[m * 768 + t];
            gx0 += s_x[0][m] * wi;
            gx1 += s_x[1][m] * wi;
            gh0 += s_h[0][m] * wh;
            gh1 += s_h[1][m] * wh;
        }
        s_gx[0][t] = gx0; s_gx[1][t] = gx1;
        s_gh[0][t] = gh0; s_gh[1][t] = gh1;
    }
    __syncthreads();

    // GRU elementwise + LN stats: threads 0..511 (warp covers single slot)
    float h = 0.f;
    int sl = (t < 512) ? (t >> 8) : 0;
    int d  = t & 255;
    if (t < 512) {
        float hprev = s_h[sl][d];
        float r = sigmoidf_(s_gx[sl][d] + s_gh[sl][d]);
        float z = sigmoidf_(s_gx[sl][d + 256] + s_gh[sl][d + 256]);
        float n = tanhf(s_gx[sl][d + 512] + r * s_gh[sl][d + 512]);
        h = (1.0f - z) * n + z * hprev;
    }
    float s1 = h, s2 = h * h;
#pragma unroll
    for (int o = 16; o > 0; o >>= 1) {
        s1 += __shfl_xor_sync(0xffffffffu, s1, o);
        s2 += __shfl_xor_sync(0xffffffffu, s2, o);
    }
    if (lane == 0 && w < 16) { wred[w] = s1; wred2[w] = s2; }
    __syncthreads();
    if (t < 512) {
        float S = 0.f, S2 = 0.f;
#pragma unroll
        for (int i = 0; i < 8; ++i) { S += wred[sl * 8 + i]; S2 += wred2[sl * 8 + i]; }
        float mean = S * (1.0f / 256.0f);
        float var  = S2 * (1.0f / 256.0f) - mean * mean;
        float sn = (h - mean) * rsqrtf(var + 1e-5f) * lng[d] + lnb[d];
        s_hn[sl][d] = h;
        s_x[sl][d]  = sn;
    }
    __syncthreads();

    // MLP layer 1: threads 0..511, one column each for BOTH slots
    if (t < 512) {
        float bb = bm1[t];
        float m0 = bb, m1 = bb;
#pragma unroll 4
        for (int j = 0; j < 256; ++j) {
            float wv = Wm1[j * 512 + t];
            m0 += s_x[0][j] * wv;
            m1 += s_x[1][j] * wv;
        }
        s_t2[0][t] = gelu_exact(m0);
        s_t2[1][t] = gelu_exact(m1);
    }
    __syncthreads();

    // MLP layer 2: threads 0..255, both slots
    if (t < 256) {
        float bb = bm2[t];
        float o0 = bb, o1 = bb;
#pragma unroll 4
        for (int j = 0; j < 512; ++j) {
            float wv = Wm2[j * 256 + t];
            o0 += s_t2[0][j] * wv;
            o1 += s_t2[1][j] * wv;
        }
        g_slots[(b * KSL + ks0) * 256 + t]     = s_hn[0][t] + o0;
        g_slots[(b * KSL + ks0 + 1) * 256 + t] = s_hn[1][t] + o1;
    }
}

// ------------------------- 9) pack outputs ---------------------------------
__global__ void writeout_kernel(float* __restrict__ out) {
    int i = blockIdx.x * 256 + threadIdx.x;   // < 1179648
    const int SZ_SLOTS = Bsz * KSL * DS;      // 65536
    const int SZ_ATTN  = Bsz * KSL * Nn;      // 1048576
    const int SZ_HALF  = Bsz * KSL * DH;      // 32768
    if (i < SZ_SLOTS) {
        out[i] = g_slots[i];
    } else if (i < SZ_SLOTS + SZ_ATTN) {
        out[i] = g_attn[i - SZ_SLOTS];
    } else if (i < SZ_SLOTS + SZ_ATTN + SZ_HALF) {
        int j = i - SZ_SLOTS - SZ_ATTN;
        int bk = j >> 7, d = j & 127;
        out[i] = g_slots[bk * 256 + d];
    } else if (i < SZ_SLOTS + SZ_ATTN + 2 * SZ_HALF) {
        int j = i - SZ_SLOTS - SZ_ATTN - SZ_HALF;
        int bk = j >> 7, d = j & 127;
        out[i] = g_slots[bk * 256 + 128 + d];
    }
}

// ------------------------- launch ------------------------------------------
extern "C" void kernel_launch(void* const* d_in, const int* in_sizes, int n_in,
                              void* d_out, int out_size) {
    const float* features = (const float*)d_in[0];
    const float* Wi1  = (const float*)d_in[1];
    const float* bi1  = (const float*)d_in[2];
    const float* Wi2  = (const float*)d_in[3];
    const float* bi2  = (const float*)d_in[4];
    const float* Wp   = (const float*)d_in[5];
    const float* bp   = (const float*)d_in[6];
    const float* ln_in_g = (const float*)d_in[7];
    const float* ln_in_b = (const float*)d_in[8];
    const float* Wqs  = (const float*)d_in[9];
    const float* Wks  = (const float*)d_in[10];
    const float* Wqt  = (const float*)d_in[11];
    const float* Wkt  = (const float*)d_in[12];
    const float* W_ih = (const float*)d_in[13];
    const float* W_hh = (const float*)d_in[14];
    const float* b_ih = (const float*)d_in[15];
    const float* b_hh = (const float*)d_in[16];
    const float* ln_g = (const float*)d_in[17];
    const float* ln_b = (const float*)d_in[18];
    const float* Wm1  = (const float*)d_in[19];
    const float* bm1  = (const float*)d_in[20];
    const float* Wm2  = (const float*)d_in[21];
    const float* bm2  = (const float*)d_in[22];
    float* out = (float*)d_out;

    cudaFuncSetAttribute(gemm_ln_tc, cudaFuncAttributeMaxDynamicSharedMemorySize,
                         GL_SMEM_BYTES);
    cudaFuncSetAttribute(kproj_tc, cudaFuncAttributeMaxDynamicSharedMemorySize,
                         KP_SMEM_BYTES);

    pool_part_kernel<<<dim3(3, 8, 32), 256>>>(features);
    pool_reduce_kernel<<<dim3(3, 32), 256>>>();
    slots_init1_kernel<<<dim3(2, 32), 256>>>(Wi1, bi1);
    slots_init2_kernel<<<dim3(8, 32), 256>>>(Wi2, bi2);
    gemm_ln_tc<<<1024, 256, GL_SMEM_BYTES>>>(features, Wp, bp, ln_in_g, ln_in_b);
    kproj_tc<<<dim3(1024, 2), 256, KP_SMEM_BYTES>>>(Wks, Wkt);

    for (int it = 0; it < NITER; ++it) {
        qproj_kernel<<<dim3(32, 8), 256>>>(Wqs, Wqt);
        logits_softmax_kernel<<<dim3(128, 32), 256>>>();
        upd1_kernel<<<dim3(16, 32), 256>>>();
        gru_mlp_kernel<<<dim3(4, 32), 768>>>(W_ih, W_hh, b_ih, b_hh,
                                             ln_g, ln_b, Wm1, bm1, Wm2, bm2);
    }
    writeout_kernel<<<4608, 256>>>(out);
}